// round 3
// baseline (speedup 1.0000x reference)
#include <cuda_runtime.h>
#include <math.h>

#define N 8192
#define D 512
#define TM 64
#define TN 64
#define BK 64
#define TNP (TN + 1)
#define KTOP 5

// Scratch (no cudaMalloc allowed)
static __device__ float g_xn[(size_t)N * D];     // 16 MB normalized rows
static __device__ float g_logrho[N];             // per-row log(mean_rho + eps)

// ---------------------------------------------------------------------------
// Kernel 1: row-normalize. One block (128 threads) per row, float4 IO.
// ---------------------------------------------------------------------------
__global__ void knorm(const float* __restrict__ x, float* __restrict__ xn) {
    int row = blockIdx.x;
    int t = threadIdx.x;  // 0..127, 128 * float4 = 512 floats
    const float4* xr = (const float4*)(x + (size_t)row * D);
    float4 v = xr[t];
    float s = v.x * v.x + v.y * v.y + v.z * v.z + v.w * v.w;
    #pragma unroll
    for (int o = 16; o; o >>= 1) s += __shfl_xor_sync(0xffffffffu, s, o);
    __shared__ float ws[4];
    if ((t & 31) == 0) ws[t >> 5] = s;
    __syncthreads();
    float tot = ws[0] + ws[1] + ws[2] + ws[3];
    float inv = rsqrtf(tot);
    float4 o4 = make_float4(v.x * inv, v.y * inv, v.z * inv, v.w * inv);
    ((float4*)(xn + (size_t)row * D))[t] = o4;
}

// ---------------------------------------------------------------------------
// Kernel 2: fused GEMM (Xn Xn^T) + per-row top-5 of dots (diag excluded).
// Grid: N/TM = 128 blocks, 256 threads. A-panel (64 rows x 512) resident in
// SMEM; stream B tiles. Each thread computes a 4x4 micro-tile; after each
// 64x64 C tile, 256 threads scan it (4 threads/row x 16 cols) keeping private
// top-5 registers; final per-row merge of the 4 partials.
// ---------------------------------------------------------------------------
__global__ void gemm_topk(const float* __restrict__ xn, float* __restrict__ logrho) {
    extern __shared__ float sm[];
    float* As = sm;                 // [D][TM]   : As[k*TM + r]   (128 KB)
    float* Bs = As + D * TM;        // [BK][TN]  : Bs[k*TN + c]   (16 KB)
    float* Cs = Bs + BK * TN;       // [TM][TNP]                  (16.25 KB)

    const int tid = threadIdx.x;
    const int brow = blockIdx.x * TM;

    // ---- Load resident A panel: 64 rows x 512 K, transposed to As[k][r] ----
    {
        int r = tid & 63;
        int kq = (tid >> 6) * 4;           // 0,4,8,12
        const float* src = xn + (size_t)(brow + r) * D;
        #pragma unroll
        for (int rep = 0; rep < 32; rep++) {
            int k = kq + rep * 16;
            float4 v = *(const float4*)(src + k);
            As[(k + 0) * TM + r] = v.x;
            As[(k + 1) * TM + r] = v.y;
            As[(k + 2) * TM + r] = v.z;
            As[(k + 3) * TM + r] = v.w;
        }
    }
    __syncthreads();

    // private partial top-5 (ascending: t0 = smallest of the kept 5)
    float t0 = -2.f, t1 = -2.f, t2 = -2.f, t3 = -2.f, t4 = -2.f;

    const int tr = (tid >> 4) * 4;  // micro-tile row offset (0..60)
    const int tc = (tid & 15) * 4;  // micro-tile col offset (0..60)
    const int rr = tid & 63;        // scan: row
    const int part = tid >> 6;      // scan: which 16-col slice
    const int rg = brow + rr;

    for (int ct = 0; ct < N / TN; ct++) {
        float acc[4][4];
        #pragma unroll
        for (int i = 0; i < 4; i++)
            #pragma unroll
            for (int j = 0; j < 4; j++) acc[i][j] = 0.f;

        for (int kb = 0; kb < D; kb += BK) {
            // load B tile: cols ct*64..+63, k = kb..kb+63 -> Bs[k][c]
            {
                int c = tid & 63;
                int kq = (tid >> 6) * 4;
                const float* src = xn + (size_t)(ct * TN + c) * D + kb;
                #pragma unroll
                for (int rep = 0; rep < 4; rep++) {
                    int k = kq + rep * 16;
                    float4 v = *(const float4*)(src + k);
                    Bs[(k + 0) * TN + c] = v.x;
                    Bs[(k + 1) * TN + c] = v.y;
                    Bs[(k + 2) * TN + c] = v.z;
                    Bs[(k + 3) * TN + c] = v.w;
                }
            }
            __syncthreads();

            #pragma unroll 8
            for (int k = 0; k < BK; k++) {
                float4 a = *(const float4*)&As[(kb + k) * TM + tr];
                float4 b = *(const float4*)&Bs[k * TN + tc];
                float av[4] = {a.x, a.y, a.z, a.w};
                float bv[4] = {b.x, b.y, b.z, b.w};
                #pragma unroll
                for (int i = 0; i < 4; i++)
                    #pragma unroll
                    for (int j = 0; j < 4; j++)
                        acc[i][j] = fmaf(av[i], bv[j], acc[i][j]);
            }
            __syncthreads();
        }

        // stash C tile to SMEM for the per-row scan
        #pragma unroll
        for (int i = 0; i < 4; i++)
            #pragma unroll
            for (int j = 0; j < 4; j++)
                Cs[(tr + i) * TNP + (tc + j)] = acc[i][j];
        __syncthreads();

        // scan 16 cols per thread, update private top-5
        #pragma unroll 4
        for (int cc = 0; cc < 16; cc++) {
            int c = part * 16 + cc;
            float v = Cs[rr * TNP + c];
            int cg = ct * TN + c;
            if (cg != rg && v > t0) {
                t0 = v;
                if (t0 > t1) { float tmp = t0; t0 = t1; t1 = tmp;
                  if (t1 > t2) { tmp = t1; t1 = t2; t2 = tmp;
                    if (t2 > t3) { tmp = t2; t2 = t3; t3 = tmp;
                      if (t3 > t4) { tmp = t3; t3 = t4; t4 = tmp; } } } }
            }
        }
        __syncthreads();  // protect Cs before next tile's writes
    }

    // ---- merge the 4 partial top-5 lists per row ----
    Cs[rr * TNP + part * 5 + 0] = t0;
    Cs[rr * TNP + part * 5 + 1] = t1;
    Cs[rr * TNP + part * 5 + 2] = t2;
    Cs[rr * TNP + part * 5 + 3] = t3;
    Cs[rr * TNP + part * 5 + 4] = t4;
    __syncthreads();

    if (tid < TM) {
        float vals[20];
        #pragma unroll
        for (int i = 0; i < 20; i++) vals[i] = Cs[tid * TNP + i];
        float sum = 0.f;
        #pragma unroll
        for (int s = 0; s < KTOP; s++) {
            int bi = 0;
            float bv = vals[0];
            #pragma unroll
            for (int i = 1; i < 20; i++)
                if (vals[i] > bv) { bv = vals[i]; bi = i; }
            vals[bi] = -9.f;
            sum += sqrtf(fmaxf(2.f - 2.f * bv, 0.f));
        }
        float mean_rho = sum * (1.f / KTOP);
        logrho[brow + tid] = logf(mean_rho + 1e-8f);
    }
}

// ---------------------------------------------------------------------------
// Kernel 3: final reduction: out = -mean(logrho)
// ---------------------------------------------------------------------------
__global__ void kred(const float* __restrict__ lr, float* __restrict__ out) {
    int t = threadIdx.x;  // 256 threads, single block
    float s = 0.f;
    for (int i = t; i < N; i += 256) s += lr[i];
    #pragma unroll
    for (int o = 16; o; o >>= 1) s += __shfl_xor_sync(0xffffffffu, s, o);
    __shared__ float ws[8];
    if ((t & 31) == 0) ws[t >> 5] = s;
    __syncthreads();
    if (t == 0) {
        float tot = 0.f;
        #pragma unroll
        for (int i = 0; i < 8; i++) tot += ws[i];
        out[0] = -tot / (float)N;
    }
}

// ---------------------------------------------------------------------------
extern "C" void kernel_launch(void* const* d_in, const int* in_sizes, int n_in,
                              void* d_out, int out_size) {
    (void)in_sizes; (void)n_in; (void)out_size;
    const float* x = (const float*)d_in[0];
    float* out = (float*)d_out;

    float* xn;     cudaGetSymbolAddress((void**)&xn, g_xn);
    float* lrho;   cudaGetSymbolAddress((void**)&lrho, g_logrho);

    const size_t smem = (size_t)(D * TM + BK * TN + TM * TNP) * sizeof(float);
    cudaFuncSetAttribute(gemm_topk, cudaFuncAttributeMaxDynamicSharedMemorySize, (int)smem);

    knorm<<<N, 128>>>(x, xn);
    gemm_topk<<<N / TM, 256, smem>>>(xn, lrho);
    kred<<<1, 256>>>(lrho, out);
}